// round 3
// baseline (speedup 1.0000x reference)
#include <cuda_runtime.h>
#include <cstdint>
#include <math.h>

#define L_SEQ   2048
#define DMODEL  1024
#define DINNER  2048
#define DSTATE  64
#define DTRANK  64
#define NBATCH  2
#define NROWS   (NBATCH * L_SEQ)          /* 4096 flattened (b,l) rows */
#define XDIM    (DTRANK + 2 * DSTATE)     /* 192 */
#define NSPLIT  8                          /* split-K factor for x_dbl GEMM */

/* ---------------- scratch (device globals; no allocations allowed) -------- */
__device__ float g_xz   [(size_t)NROWS * 2 * DINNER];   /* 64 MB: [x | z] */
__device__ float g_xssm [(size_t)NROWS * DINNER];       /* 32 MB */
__device__ float g_xdbl [(size_t)NROWS * XDIM];         /*  3 MB */
__device__ float g_part [(size_t)NSPLIT * NROWS * XDIM];/* 24 MB split-K partials */
__device__ float g_dt   [(size_t)NROWS * DINNER];       /* 32 MB */
__device__ float g_y    [(size_t)NROWS * DINNER];       /* 32 MB */

/* ---------------- tiled fp32 GEMM (row-major A[M,K] * B[K,N] = C[M,N]) ---- */
enum { EPI_STORE = 0, EPI_SOFTPLUS = 1 };

template <int BM, int BN, int BK, int TM, int TN, int EPI>
__global__ __launch_bounds__(256)
void sgemm_kernel(const float* __restrict__ A, const float* __restrict__ B,
                  float* __restrict__ C, const float* __restrict__ bias,
                  int M, int N, int K, int lda, int ldb, int ldc)
{
    static_assert(BM * BK == 1024 && BK * BN == 1024, "one float4 per thread");
    static_assert((BM / TM) * (BN / TN) == 256, "256 threads");

    __shared__ __align__(16) float As[BK][BM];
    __shared__ __align__(16) float Bs[BK][BN];

    const int tid = threadIdx.x;
    const int m0  = blockIdx.y * BM;
    const int n0  = blockIdx.x * BN;
    const int kchunk = K / gridDim.z;
    const int kbeg   = blockIdx.z * kchunk;
    C += (size_t)blockIdx.z * (size_t)M * (size_t)ldc;   /* split-K partial slab */

    const int tx = tid & 15;         /* 16 cols of threads */
    const int ty = tid >> 4;         /* 16 rows of threads */

    const int APR  = BK / 4;                 /* float4s per A-tile row   */
    const int arow = tid / APR;
    const int acol = (tid % APR) * 4;
    const int BPR  = BN / 4;                 /* float4s per B-tile row   */
    const int brow = tid / BPR;
    const int bcol = (tid % BPR) * 4;

    float acc[TM][TN];
#pragma unroll
    for (int i = 0; i < TM; i++)
#pragma unroll
        for (int j = 0; j < TN; j++) acc[i][j] = 0.f;

    for (int kt = kbeg; kt < kbeg + kchunk; kt += BK) {
        /* stage A (transposed into As[k][m]) */
        float4 av = *reinterpret_cast<const float4*>(
            &A[(size_t)(m0 + arow) * lda + kt + acol]);
        As[acol + 0][arow] = av.x;
        As[acol + 1][arow] = av.y;
        As[acol + 2][arow] = av.z;
        As[acol + 3][arow] = av.w;
        /* stage B */
        float4 bv = make_float4(0.f, 0.f, 0.f, 0.f);
        if (n0 + bcol < N)   /* N is always a multiple of 4; full-or-none */
            bv = *reinterpret_cast<const float4*>(
                &B[(size_t)(kt + brow) * ldb + n0 + bcol]);
        *reinterpret_cast<float4*>(&Bs[brow][bcol]) = bv;
        __syncthreads();

#pragma unroll
        for (int k = 0; k < BK; k++) {
            float ra[TM], rb[TN];
#pragma unroll
            for (int i = 0; i < TM; i += 4) {
                float4 v = *reinterpret_cast<const float4*>(&As[k][ty * TM + i]);
                ra[i] = v.x; ra[i + 1] = v.y; ra[i + 2] = v.z; ra[i + 3] = v.w;
            }
#pragma unroll
            for (int j = 0; j < TN; j += 4) {
                float4 v = *reinterpret_cast<const float4*>(&Bs[k][tx * TN + j]);
                rb[j] = v.x; rb[j + 1] = v.y; rb[j + 2] = v.z; rb[j + 3] = v.w;
            }
#pragma unroll
            for (int i = 0; i < TM; i++)
#pragma unroll
                for (int j = 0; j < TN; j++)
                    acc[i][j] = fmaf(ra[i], rb[j], acc[i][j]);
        }
        __syncthreads();
    }

#pragma unroll
    for (int i = 0; i < TM; i++) {
        const int gm = m0 + ty * TM + i;
#pragma unroll
        for (int j = 0; j < TN; j++) {
            const int gn = n0 + tx * TN + j;
            if (gn < N) {
                float v = acc[i][j];
                if (EPI == EPI_SOFTPLUS) {
                    v += bias[gn];
                    v = (v > 20.f) ? v : log1pf(expf(v));
                }
                C[(size_t)gm * ldc + gn] = v;
            }
        }
    }
}

/* ---------------- reduce NSPLIT split-K partials ------------------------- */
__global__ __launch_bounds__(256)
void reduce_split_kernel(float* __restrict__ dst,
                         const float* __restrict__ src, int n)
{
    int i = blockIdx.x * blockDim.x + threadIdx.x;
    if (i < n) {
        float s = 0.f;
#pragma unroll
        for (int p = 0; p < NSPLIT; p++) s += src[(size_t)p * n + i];
        dst[i] = s;
    }
}

/* ---------------- causal depthwise conv (K=4) + bias + SiLU --------------- */
__global__ __launch_bounds__(256)
void conv_silu_kernel(const float* __restrict__ convw,
                      const float* __restrict__ convb)
{
    int idx = blockIdx.x * blockDim.x + threadIdx.x;
    if (idx >= NROWS * DINNER) return;
    const int d   = idx & (DINNER - 1);
    const int row = idx >> 11;                 /* b*L + l */
    const int l   = row & (L_SEQ - 1);
    const int b   = row >> 11;
    float acc = convb[d];
#pragma unroll
    for (int k = 0; k < 4; k++) {
        const int ls = l - 3 + k;
        if (ls >= 0)
            acc = fmaf(convw[d * 4 + k],
                       g_xz[(size_t)(b * L_SEQ + ls) * (2 * DINNER) + d], acc);
    }
    acc = acc / (1.f + __expf(-acc));          /* SiLU */
    g_xssm[idx] = acc;
}

/* ---------------- selective scan ------------------------------------------
 * One warp per (b, d) channel; lane owns states n = 2*lane, 2*lane+1.
 * Block = 8 warps (8 channels of the same batch) sharing a staged B/C tile. */
#define SCAN_T 64
#define CPB    8
__global__ __launch_bounds__(256)
void scan_kernel(const float* __restrict__ A_log)
{
    __shared__ __align__(8) float sBC[SCAN_T][2 * DSTATE];  /* [t][B(64)|C(64)] */
    __shared__ float sdt[SCAN_T][CPB];
    __shared__ float sx [SCAN_T][CPB];
    __shared__ float sy [SCAN_T][CPB];

    const int b    = blockIdx.y;
    const int d0   = blockIdx.x * CPB;
    const int tid  = threadIdx.x;
    const int w    = tid >> 5;
    const int lane = tid & 31;
    const int d    = d0 + w;

    const float a0 = -expf(A_log[(size_t)d * DSTATE + 2 * lane]);
    const float a1 = -expf(A_log[(size_t)d * DSTATE + 2 * lane + 1]);
    float h0 = 0.f, h1 = 0.f;
    const int rowbase = b * L_SEQ;

    for (int t0 = 0; t0 < L_SEQ; t0 += SCAN_T) {
        for (int i = tid; i < SCAN_T * 2 * DSTATE; i += 256) {
            const int t = i >> 7, j = i & 127;
            sBC[t][j] = g_xdbl[(size_t)(rowbase + t0 + t) * XDIM + DTRANK + j];
        }
        for (int i = tid; i < SCAN_T * CPB; i += 256) {
            const int t = i / CPB, c = i % CPB;
            const size_t r = (size_t)(rowbase + t0 + t) * DINNER + d0 + c;
            sdt[t][c] = g_dt[r];
            sx [t][c] = g_xssm[r];
        }
        __syncthreads();

        for (int t = 0; t < SCAN_T; t++) {
            const float dtv = sdt[t][w];
            const float xv  = sx [t][w];
            const float2 Bv = *reinterpret_cast<const float2*>(&sBC[t][2 * lane]);
            const float2 Cv = *reinterpret_cast<const float2*>(&sBC[t][DSTATE + 2 * lane]);
            const float dA0 = __expf(a0 * dtv);
            const float dA1 = __expf(a1 * dtv);
            const float dbx = dtv * xv;
            h0 = fmaf(dA0, h0, dbx * Bv.x);
            h1 = fmaf(dA1, h1, dbx * Bv.y);
            float s = fmaf(h1, Cv.y, h0 * Cv.x);
            s += __shfl_xor_sync(0xffffffffu, s, 16);
            s += __shfl_xor_sync(0xffffffffu, s, 8);
            s += __shfl_xor_sync(0xffffffffu, s, 4);
            s += __shfl_xor_sync(0xffffffffu, s, 2);
            s += __shfl_xor_sync(0xffffffffu, s, 1);
            if (lane == 0) sy[t][w] = s;
        }
        __syncthreads();

        for (int i = tid; i < SCAN_T * CPB; i += 256) {
            const int t = i / CPB, c = i % CPB;
            g_y[(size_t)(rowbase + t0 + t) * DINNER + d0 + c] = sy[t][c];
        }
        /* next tile's staging syncthreads orders the sy reads vs rewrites */
        __syncthreads();
    }
}

/* ---------------- gating epilogue: y = (y + x_ssm*D) * silu(z) ------------ */
__global__ __launch_bounds__(256)
void gate_kernel(const float* __restrict__ Dvec)
{
    int idx = blockIdx.x * blockDim.x + threadIdx.x;
    if (idx >= NROWS * DINNER) return;
    const int d   = idx & (DINNER - 1);
    const int row = idx >> 11;
    const float z = g_xz[(size_t)row * (2 * DINNER) + DINNER + d];
    const float v = g_y[idx] + g_xssm[idx] * Dvec[d];
    g_y[idx] = v * (z / (1.f + __expf(-z)));
}

/* ---------------- host orchestration -------------------------------------- */
extern "C" void kernel_launch(void* const* d_in, const int* in_sizes, int n_in,
                              void* d_out, int out_size)
{
    const float* u     = (const float*)d_in[0];
    const float* W_in  = (const float*)d_in[1];
    const float* convw = (const float*)d_in[2];
    const float* convb = (const float*)d_in[3];
    const float* W_x   = (const float*)d_in[4];
    const float* W_dt  = (const float*)d_in[5];
    const float* b_dt  = (const float*)d_in[6];
    const float* A_log = (const float*)d_in[7];
    const float* Dvec  = (const float*)d_in[8];
    const float* W_out = (const float*)d_in[9];
    float* out = (float*)d_out;

    void *p_xz, *p_xssm, *p_xdbl, *p_part, *p_dt, *p_y;
    cudaGetSymbolAddress(&p_xz,   g_xz);
    cudaGetSymbolAddress(&p_xssm, g_xssm);
    cudaGetSymbolAddress(&p_xdbl, g_xdbl);
    cudaGetSymbolAddress(&p_part, g_part);
    cudaGetSymbolAddress(&p_dt,   g_dt);
    cudaGetSymbolAddress(&p_y,    g_y);
    float* xz   = (float*)p_xz;
    float* xssm = (float*)p_xssm;
    float* xdbl = (float*)p_xdbl;
    float* part = (float*)p_part;
    float* dtb  = (float*)p_dt;
    float* yb   = (float*)p_y;

    const int threads = 256;
    const int n_elem  = NROWS * DINNER;

    /* 1. xz = u @ W_in                         [4096,1024]x[1024,4096] */
    sgemm_kernel<128, 128, 8, 8, 8, EPI_STORE>
        <<<dim3(4096 / 128, NROWS / 128, 1), threads>>>(
            u, W_in, xz, nullptr, NROWS, 2 * DINNER, DMODEL,
            DMODEL, 2 * DINNER, 2 * DINNER);

    /* 2. causal depthwise conv + SiLU -> x_ssm */
    conv_silu_kernel<<<n_elem / threads, threads>>>(convw, convb);

    /* 3. x_dbl = x_ssm @ W_x (split-K=8, deterministic partials)  N=192 */
    sgemm_kernel<64, 64, 16, 4, 4, EPI_STORE>
        <<<dim3(XDIM / 64, NROWS / 64, NSPLIT), threads>>>(
            xssm, W_x, part, nullptr, NROWS, XDIM, DINNER,
            DINNER, XDIM, XDIM);
    reduce_split_kernel<<<(NROWS * XDIM + threads - 1) / threads, threads>>>(
        xdbl, part, NROWS * XDIM);

    /* 4. dt = softplus(dt_r @ W_dt + b_dt)     K=64, A has lda=192 */
    sgemm_kernel<64, 64, 16, 4, 4, EPI_SOFTPLUS>
        <<<dim3(DINNER / 64, NROWS / 64, 1), threads>>>(
            xdbl, W_dt, dtb, b_dt, NROWS, DINNER, DTRANK,
            XDIM, DINNER, DINNER);

    /* 5. selective scan -> y */
    scan_kernel<<<dim3(DINNER / CPB, NBATCH), threads>>>(A_log);

    /* 6. y = (y + x_ssm*D) * silu(z) */
    gate_kernel<<<n_elem / threads, threads>>>(Dvec);

    /* 7. out = y @ W_out                       [4096,2048]x[2048,1024] */
    sgemm_kernel<128, 128, 8, 8, 8, EPI_STORE>
        <<<dim3(DMODEL / 128, NROWS / 128, 1), threads>>>(
            yb, W_out, out, nullptr, NROWS, DMODEL, DINNER,
            DINNER, DMODEL, DMODEL);
}

// round 7
// speedup vs baseline: 1.0631x; 1.0631x over previous
#include <cuda_runtime.h>
#include <cstdint>
#include <math.h>

#define L_SEQ   2048
#define DMODEL  1024
#define DINNER  2048
#define DSTATE  64
#define DTRANK  64
#define NBATCH  2
#define NROWS   (NBATCH * L_SEQ)          /* 4096 flattened (b,l) rows */
#define XDIM    (DTRANK + 2 * DSTATE)     /* 192 */
#define NSPLIT  8                          /* split-K factor for x_dbl GEMM */

/* ---------------- scratch (device globals; no allocations allowed) -------- */
__device__ float g_xz   [(size_t)NROWS * 2 * DINNER];   /* 64 MB: [x | z] */
__device__ float g_xssm [(size_t)NROWS * DINNER];       /* 32 MB */
__device__ float g_xdbl [(size_t)NROWS * XDIM];         /*  3 MB */
__device__ float g_part [(size_t)NSPLIT * NROWS * XDIM];/* 24 MB split-K partials */
__device__ float g_dt   [(size_t)NROWS * DINNER];       /* 32 MB */
__device__ float g_y    [(size_t)NROWS * DINNER];       /* 32 MB */

/* ---------------- packed f32x2 helpers (sm_100+ family PTX) --------------- */
__device__ __forceinline__ unsigned long long ffma2(unsigned long long a,
                                                    unsigned long long b,
                                                    unsigned long long c)
{
    unsigned long long d;
    asm("fma.rn.f32x2 %0, %1, %2, %3;" : "=l"(d) : "l"(a), "l"(b), "l"(c));
    return d;
}
__device__ __forceinline__ unsigned long long pack2(float x)
{
    unsigned long long d;
    unsigned int b = __float_as_uint(x);
    asm("mov.b64 %0, {%1, %2};" : "=l"(d) : "r"(b), "r"(b));
    return d;
}
__device__ __forceinline__ void unpack2(unsigned long long v, float& lo, float& hi)
{
    unsigned int a, b;
    asm("mov.b64 {%0, %1}, %2;" : "=r"(a), "=r"(b) : "l"(v));
    lo = __uint_as_float(a);
    hi = __uint_as_float(b);
}

/* ---------------- tiled fp32x2 GEMM (row-major A[M,K]*B[K,N]=C[M,N]) ------ */
enum { EPI_STORE = 0, EPI_SOFTPLUS = 1 };

template <int BM, int BN, int BK, int TM, int TN, int EPI>
__global__ __launch_bounds__(256)
void sgemm_kernel(const float* __restrict__ A, const float* __restrict__ B,
                  float* __restrict__ C, const float* __restrict__ bias,
                  int M, int N, int K, int lda, int ldb, int ldc)
{
    static_assert((BM * BK) % 1024 == 0 && (BN * BK) % 1024 == 0, "tile loads");
    static_assert((BM / TM) * (BN / TN) == 256, "256 threads");
    static_assert(TN % 2 == 0 && TM % 4 == 0, "packing");

    __shared__ __align__(16) float As[BK][BM];
    __shared__ __align__(16) float Bs[BK][BN];

    const int tid = threadIdx.x;
    const int m0  = blockIdx.y * BM;
    const int n0  = blockIdx.x * BN;
    const int kchunk = K / gridDim.z;
    const int kbeg   = blockIdx.z * kchunk;
    C += (size_t)blockIdx.z * (size_t)M * (size_t)ldc;   /* split-K partial slab */

    const int tx = tid & 15;         /* 16 cols of threads */
    const int ty = tid >> 4;         /* 16 rows of threads */

    const int APR = BK / 4;                  /* float4s per A-tile row */
    const int BPR = BN / 4;                  /* float4s per B-tile row */
    const int AIT = (BM * BK) / 1024;        /* A float4 loads per thread */
    const int BIT = (BN * BK) / 1024;        /* B float4 loads per thread */

    unsigned long long acc2[TM][TN / 2];
#pragma unroll
    for (int i = 0; i < TM; i++)
#pragma unroll
        for (int j = 0; j < TN / 2; j++) acc2[i][j] = 0ull;

    for (int kt = kbeg; kt < kbeg + kchunk; kt += BK) {
        /* stage A (transposed into As[k][m]) */
#pragma unroll
        for (int it = 0; it < AIT; it++) {
            const int u    = tid + it * 256;
            const int arow = u / APR;
            const int acol = (u % APR) * 4;
            float4 av = *reinterpret_cast<const float4*>(
                &A[(size_t)(m0 + arow) * lda + kt + acol]);
            As[acol + 0][arow] = av.x;
            As[acol + 1][arow] = av.y;
            As[acol + 2][arow] = av.z;
            As[acol + 3][arow] = av.w;
        }
        /* stage B */
#pragma unroll
        for (int it = 0; it < BIT; it++) {
            const int u    = tid + it * 256;
            const int brow = u / BPR;
            const int bcol = (u % BPR) * 4;
            float4 bv = make_float4(0.f, 0.f, 0.f, 0.f);
            if (n0 + bcol < N)   /* N multiple of 4; full-or-none */
                bv = *reinterpret_cast<const float4*>(
                    &B[(size_t)(kt + brow) * ldb + n0 + bcol]);
            *reinterpret_cast<float4*>(&Bs[brow][bcol]) = bv;
        }
        __syncthreads();

#pragma unroll
        for (int k = 0; k < BK; k++) {
            unsigned long long ra2[TM];
#pragma unroll
            for (int i = 0; i < TM; i += 4) {
                float4 v = *reinterpret_cast<const float4*>(&As[k][ty * TM + i]);
                ra2[i + 0] = pack2(v.x);
                ra2[i + 1] = pack2(v.y);
                ra2[i + 2] = pack2(v.z);
                ra2[i + 3] = pack2(v.w);
            }
            unsigned long long rb2[TN / 2];
#pragma unroll
            for (int j = 0; j < TN / 2; j += 2) {
                ulonglong2 bv = *reinterpret_cast<const ulonglong2*>(
                    &Bs[k][tx * TN + j * 2]);
                rb2[j + 0] = bv.x;
                rb2[j + 1] = bv.y;
            }
#pragma unroll
            for (int i = 0; i < TM; i++)
#pragma unroll
                for (int j = 0; j < TN / 2; j++)
                    acc2[i][j] = ffma2(ra2[i], rb2[j], acc2[i][j]);
        }
        __syncthreads();
    }

#pragma unroll
    for (int i = 0; i < TM; i++) {
        const int gm = m0 + ty * TM + i;
#pragma unroll
        for (int j = 0; j < TN / 2; j++) {
            float v0, v1;
            unpack2(acc2[i][j], v0, v1);
            const int gn = n0 + tx * TN + 2 * j;
            if (gn < N) {
                if (EPI == EPI_SOFTPLUS) {
                    v0 += bias[gn];
                    v0 = (v0 > 20.f) ? v0 : log1pf(expf(v0));
                }
                C[(size_t)gm * ldc + gn] = v0;
            }
            if (gn + 1 < N) {
                if (EPI == EPI_SOFTPLUS) {
                    v1 += bias[gn + 1];
                    v1 = (v1 > 20.f) ? v1 : log1pf(expf(v1));
                }
                C[(size_t)gm * ldc + gn + 1] = v1;
            }
        }
    }
}

/* ---------------- reduce NSPLIT split-K partials ------------------------- */
__global__ __launch_bounds__(256)
void reduce_split_kernel(float* __restrict__ dst,
                         const float* __restrict__ src, int n)
{
    int i = blockIdx.x * blockDim.x + threadIdx.x;
    if (i < n) {
        float s = 0.f;
#pragma unroll
        for (int p = 0; p < NSPLIT; p++) s += src[(size_t)p * n + i];
        dst[i] = s;
    }
}

/* ---------------- causal depthwise conv (K=4) + bias + SiLU --------------- */
__global__ __launch_bounds__(256)
void conv_silu_kernel(const float* __restrict__ convw,
                      const float* __restrict__ convb)
{
    int idx = blockIdx.x * blockDim.x + threadIdx.x;
    if (idx >= NROWS * DINNER) return;
    const int d   = idx & (DINNER - 1);
    const int row = idx >> 11;                 /* b*L + l */
    const int l   = row & (L_SEQ - 1);
    const int b   = row >> 11;
    float acc = convb[d];
#pragma unroll
    for (int k = 0; k < 4; k++) {
        const int ls = l - 3 + k;
        if (ls >= 0)
            acc = fmaf(convw[d * 4 + k],
                       g_xz[(size_t)(b * L_SEQ + ls) * (2 * DINNER) + d], acc);
    }
    acc = acc / (1.f + __expf(-acc));          /* SiLU */
    g_xssm[idx] = acc;
}

/* ---------------- selective scan ------------------------------------------
 * One warp per (b, d) channel; lane owns states n = 2*lane, 2*lane+1.
 * Block = 8 warps (8 channels of the same batch) sharing a staged B/C tile. */
#define SCAN_T 64
#define CPB    8
__global__ __launch_bounds__(256)
void scan_kernel(const float* __restrict__ A_log)
{
    __shared__ __align__(8) float sBC[SCAN_T][2 * DSTATE];  /* [t][B(64)|C(64)] */
    __shared__ float sdt[SCAN_T][CPB];
    __shared__ float sx [SCAN_T][CPB];
    __shared__ float sy [SCAN_T][CPB];

    const int b    = blockIdx.y;
    const int d0   = blockIdx.x * CPB;
    const int tid  = threadIdx.x;
    const int w    = tid >> 5;
    const int lane = tid & 31;
    const int d    = d0 + w;

    const float a0 = -expf(A_log[(size_t)d * DSTATE + 2 * lane]);
    const float a1 = -expf(A_log[(size_t)d * DSTATE + 2 * lane + 1]);
    float h0 = 0.f, h1 = 0.f;
    const int rowbase = b * L_SEQ;

    for (int t0 = 0; t0 < L_SEQ; t0 += SCAN_T) {
        for (int i = tid; i < SCAN_T * 2 * DSTATE; i += 256) {
            const int t = i >> 7, j = i & 127;
            sBC[t][j] = g_xdbl[(size_t)(rowbase + t0 + t) * XDIM + DTRANK + j];
        }
        for (int i = tid; i < SCAN_T * CPB; i += 256) {
            const int t = i / CPB, c = i % CPB;
            const size_t r = (size_t)(rowbase + t0 + t) * DINNER + d0 + c;
            sdt[t][c] = g_dt[r];
            sx [t][c] = g_xssm[r];
        }
        __syncthreads();

        for (int t = 0; t < SCAN_T; t++) {
            const float dtv = sdt[t][w];
            const float xv  = sx [t][w];
            const float2 Bv = *reinterpret_cast<const float2*>(&sBC[t][2 * lane]);
            const float2 Cv = *reinterpret_cast<const float2*>(&sBC[t][DSTATE + 2 * lane]);
            const float dA0 = __expf(a0 * dtv);
            const float dA1 = __expf(a1 * dtv);
            const float dbx = dtv * xv;
            h0 = fmaf(dA0, h0, dbx * Bv.x);
            h1 = fmaf(dA1, h1, dbx * Bv.y);
            float s = fmaf(h1, Cv.y, h0 * Cv.x);
            s += __shfl_xor_sync(0xffffffffu, s, 16);
            s += __shfl_xor_sync(0xffffffffu, s, 8);
            s += __shfl_xor_sync(0xffffffffu, s, 4);
            s += __shfl_xor_sync(0xffffffffu, s, 2);
            s += __shfl_xor_sync(0xffffffffu, s, 1);
            if (lane == 0) sy[t][w] = s;
        }
        __syncthreads();

        for (int i = tid; i < SCAN_T * CPB; i += 256) {
            const int t = i / CPB, c = i % CPB;
            g_y[(size_t)(rowbase + t0 + t) * DINNER + d0 + c] = sy[t][c];
        }
        /* next tile's staging syncthreads orders the sy reads vs rewrites */
        __syncthreads();
    }
}

/* ---------------- gating epilogue: y = (y + x_ssm*D) * silu(z) ------------ */
__global__ __launch_bounds__(256)
void gate_kernel(const float* __restrict__ Dvec)
{
    int idx = blockIdx.x * blockDim.x + threadIdx.x;
    if (idx >= NROWS * DINNER) return;
    const int d   = idx & (DINNER - 1);
    const int row = idx >> 11;
    const float z = g_xz[(size_t)row * (2 * DINNER) + DINNER + d];
    const float v = g_y[idx] + g_xssm[idx] * Dvec[d];
    g_y[idx] = v * (z / (1.f + __expf(-z)));
}

/* ---------------- host orchestration -------------------------------------- */
extern "C" void kernel_launch(void* const* d_in, const int* in_sizes, int n_in,
                              void* d_out, int out_size)
{
    const float* u     = (const float*)d_in[0];
    const float* W_in  = (const float*)d_in[1];
    const float* convw = (const float*)d_in[2];
    const float* convb = (const float*)d_in[3];
    const float* W_x   = (const float*)d_in[4];
    const float* W_dt  = (const float*)d_in[5];
    const float* b_dt  = (const float*)d_in[6];
    const float* A_log = (const float*)d_in[7];
    const float* Dvec  = (const float*)d_in[8];
    const float* W_out = (const float*)d_in[9];
    float* out = (float*)d_out;

    void* p;
    cudaGetSymbolAddress(&p, g_xz);    float* xz   = (float*)p;
    cudaGetSymbolAddress(&p, g_xssm);  float* xssm = (float*)p;
    cudaGetSymbolAddress(&p, g_xdbl);  float* xdbl = (float*)p;
    cudaGetSymbolAddress(&p, g_part);  float* part = (float*)p;
    cudaGetSymbolAddress(&p, g_dt);    float* dtb  = (float*)p;
    cudaGetSymbolAddress(&p, g_y);     float* yb   = (float*)p;

    const int threads = 256;
    const int n_elem  = NROWS * DINNER;

    /* 1. xz = u @ W_in                         [4096,1024]x[1024,4096] */
    sgemm_kernel<128, 128, 16, 8, 8, EPI_STORE>
        <<<dim3(4096 / 128, NROWS / 128, 1), threads>>>(
            u, W_in, xz, nullptr, NROWS, 2 * DINNER, DMODEL,
            DMODEL, 2 * DINNER, 2 * DINNER);

    /* 2. causal depthwise conv + SiLU -> x_ssm */
    conv_silu_kernel<<<n_elem / threads, threads>>>(convw, convb);

    /* 3. x_dbl = x_ssm @ W_x (split-K=8, deterministic partials)  N=192 */
    sgemm_kernel<64, 64, 16, 4, 4, EPI_STORE>
        <<<dim3(XDIM / 64, NROWS / 64, NSPLIT), threads>>>(
            xssm, W_x, part, nullptr, NROWS, XDIM, DINNER,
            DINNER, XDIM, XDIM);
    reduce_split_kernel<<<(NROWS * XDIM + threads - 1) / threads, threads>>>(
        xdbl, part, NROWS * XDIM);

    /* 4. dt = softplus(dt_r @ W_dt + b_dt)     K=64, A has lda=192 */
    sgemm_kernel<64, 64, 16, 4, 4, EPI_SOFTPLUS>
        <<<dim3(DINNER / 64, NROWS / 64, 1), threads>>>(
            xdbl, W_dt, dtb, b_dt, NROWS, DINNER, DTRANK,
            XDIM, DINNER, DINNER);

    /* 5. selective scan -> y */
    scan_kernel<<<dim3(DINNER / CPB, NBATCH), threads>>>(A_log);

    /* 6. y = (y + x_ssm*D) * silu(z) */
    gate_kernel<<<n_elem / threads, threads>>>(Dvec);

    /* 7. out = y @ W_out                       [4096,2048]x[2048,1024] */
    sgemm_kernel<128, 128, 16, 8, 8, EPI_STORE>
        <<<dim3(DMODEL / 128, NROWS / 128, 1), threads>>>(
            yb, W_out, out, nullptr, NROWS, DMODEL, DINNER,
            DINNER, DMODEL, DMODEL);
}

// round 11
// speedup vs baseline: 1.6724x; 1.5732x over previous
#include <cuda_runtime.h>
#include <cuda_bf16.h>
#include <cstdint>
#include <math.h>

#define L_SEQ   2048
#define DMODEL  1024
#define DINNER  2048
#define DSTATE  64
#define DTRANK  64
#define NBATCH  2
#define NROWS   (NBATCH * L_SEQ)          /* 4096 flattened (b,l) rows */
#define XDIM    (DTRANK + 2 * DSTATE)     /* 192 */
#define NSPLIT  8                          /* split-K factor for x_dbl GEMM */

/* -------- scratch (device globals; explicit 256B alignment: the bf16
 * arrays' natural alignment is only 2B, and we do 16B vector accesses) ----- */
__device__ __align__(256) float g_xz   [(size_t)NROWS * 2 * DINNER];
__device__ __align__(256) float g_xssm [(size_t)NROWS * DINNER];
__device__ __align__(256) float g_xdbl [(size_t)NROWS * XDIM];
__device__ __align__(256) float g_part [(size_t)NSPLIT * NROWS * XDIM];
__device__ __align__(256) float g_dt   [(size_t)NROWS * DINNER];
__device__ __align__(256) float g_y    [(size_t)NROWS * DINNER];

/* bf16-split operands for HMMA GEMMs */
__device__ __align__(256) __nv_bfloat16 g_uhi [(size_t)NROWS * DMODEL];
__device__ __align__(256) __nv_bfloat16 g_ulo [(size_t)NROWS * DMODEL];
__device__ __align__(256) __nv_bfloat16 g_Wihi[(size_t)(2 * DINNER) * DMODEL];
__device__ __align__(256) __nv_bfloat16 g_Wilo[(size_t)(2 * DINNER) * DMODEL];
__device__ __align__(256) __nv_bfloat16 g_Wohi[(size_t)DMODEL * DINNER];
__device__ __align__(256) __nv_bfloat16 g_Wolo[(size_t)DMODEL * DINNER];
__device__ __align__(256) __nv_bfloat16 g_yhi [(size_t)NROWS * DINNER];
__device__ __align__(256) __nv_bfloat16 g_ylo [(size_t)NROWS * DINNER];

__device__ __forceinline__ void split2(float v, __nv_bfloat16& h, __nv_bfloat16& l)
{
    h = __float2bfloat16(v);
    l = __float2bfloat16(v - __bfloat162float(h));
}

/* ==================== HMMA bf16-split GEMM (mma.sync) =====================
 * C[M,N] = A[M,K] @ W[K,N], A as (Ahi,Alo) [M,K] bf16 row-major, W given
 * transposed (Bhi,Blo) [N,K] bf16 row-major (= col-major B for mma "row.col").
 * D = Ahi*Bhi + Ahi*Blo + Alo*Bhi, fp32 accum. CTA 128x128, BK=32, 8 warps. */
#define HBM 128
#define HBN 128
#define HBK 32
#define HPAD 40   /* smem row stride (bf16): 20 words -> conflict-free frags */

__device__ __forceinline__ void mma16816(float* c, const unsigned* a,
                                         const unsigned* b)
{
    asm volatile(
        "mma.sync.aligned.m16n8k16.row.col.f32.bf16.bf16.f32 "
        "{%0,%1,%2,%3}, {%4,%5,%6,%7}, {%8,%9}, {%0,%1,%2,%3};"
        : "+f"(c[0]), "+f"(c[1]), "+f"(c[2]), "+f"(c[3])
        : "r"(a[0]), "r"(a[1]), "r"(a[2]), "r"(a[3]), "r"(b[0]), "r"(b[1]));
}

__global__ __launch_bounds__(256, 2)
void hmma_gemm_kernel(const __nv_bfloat16* __restrict__ Ahi,
                      const __nv_bfloat16* __restrict__ Alo,
                      const __nv_bfloat16* __restrict__ Bhi,
                      const __nv_bfloat16* __restrict__ Blo,
                      float* __restrict__ C, int M, int N, int K)
{
    __shared__ __align__(16) __nv_bfloat16 sAh[HBM][HPAD];
    __shared__ __align__(16) __nv_bfloat16 sAl[HBM][HPAD];
    __shared__ __align__(16) __nv_bfloat16 sBh[HBN][HPAD];
    __shared__ __align__(16) __nv_bfloat16 sBl[HBN][HPAD];

    const int tid  = threadIdx.x;
    const int wid  = tid >> 5;
    const int lane = tid & 31;
    const int grp  = lane >> 2;          /* 0..7  */
    const int tig  = lane & 3;           /* 0..3  */
    const int wm   = wid & 1;            /* 2 warps in m */
    const int wn   = wid >> 1;           /* 4 warps in n */
    const int m0   = blockIdx.y * HBM;
    const int n0   = blockIdx.x * HBN;

    float acc[4][4][4];                  /* [mt][nt][reg] */
#pragma unroll
    for (int i = 0; i < 4; i++)
#pragma unroll
        for (int j = 0; j < 4; j++)
#pragma unroll
            for (int r = 0; r < 4; r++) acc[i][j][r] = 0.f;

    for (int kt = 0; kt < K; kt += HBK) {
        /* stage: 128 rows x 4 quads (8 bf16 = 16B) for A and B, hi+lo */
#pragma unroll
        for (int it = 0; it < 2; it++) {
            const int u   = tid + it * 256;
            const int row = u >> 2;
            const int q   = (u & 3) * 8;
            const size_t ga = (size_t)(m0 + row) * K + kt + q;
            const size_t gb = (size_t)(n0 + row) * K + kt + q;
            *(uint4*)&sAh[row][q] = *(const uint4*)(Ahi + ga);
            *(uint4*)&sAl[row][q] = *(const uint4*)(Alo + ga);
            *(uint4*)&sBh[row][q] = *(const uint4*)(Bhi + gb);
            *(uint4*)&sBl[row][q] = *(const uint4*)(Blo + gb);
        }
        __syncthreads();

#pragma unroll
        for (int ks = 0; ks < 2; ks++) {
            const int kb = ks * 16;
            /* B fragments for the 4 n8 tiles (hi & lo) */
            unsigned bh[4][2], bl[4][2];
#pragma unroll
            for (int nt = 0; nt < 4; nt++) {
                const int brow = wn * 32 + nt * 8 + grp;
                bh[nt][0] = *(const unsigned*)&sBh[brow][kb + 2 * tig];
                bh[nt][1] = *(const unsigned*)&sBh[brow][kb + 8 + 2 * tig];
                bl[nt][0] = *(const unsigned*)&sBl[brow][kb + 2 * tig];
                bl[nt][1] = *(const unsigned*)&sBl[brow][kb + 8 + 2 * tig];
            }
#pragma unroll
            for (int mt = 0; mt < 4; mt++) {
                const int ar = wm * 64 + mt * 16 + grp;
                unsigned ah[4], al[4];
                ah[0] = *(const unsigned*)&sAh[ar][kb + 2 * tig];
                ah[1] = *(const unsigned*)&sAh[ar + 8][kb + 2 * tig];
                ah[2] = *(const unsigned*)&sAh[ar][kb + 8 + 2 * tig];
                ah[3] = *(const unsigned*)&sAh[ar + 8][kb + 8 + 2 * tig];
                al[0] = *(const unsigned*)&sAl[ar][kb + 2 * tig];
                al[1] = *(const unsigned*)&sAl[ar + 8][kb + 2 * tig];
                al[2] = *(const unsigned*)&sAl[ar][kb + 8 + 2 * tig];
                al[3] = *(const unsigned*)&sAl[ar + 8][kb + 8 + 2 * tig];
#pragma unroll
                for (int nt = 0; nt < 4; nt++) {
                    mma16816(acc[mt][nt], ah, bh[nt]);
                    mma16816(acc[mt][nt], ah, bl[nt]);
                    mma16816(acc[mt][nt], al, bh[nt]);
                }
            }
        }
        __syncthreads();
    }

    /* epilogue: each (mt,nt): d0,d1 -> (row, col..col+1); d2,d3 -> row+8 */
#pragma unroll
    for (int mt = 0; mt < 4; mt++) {
        const int row = m0 + wm * 64 + mt * 16 + grp;
#pragma unroll
        for (int nt = 0; nt < 4; nt++) {
            const int col = n0 + wn * 32 + nt * 8 + 2 * tig;
            float2 v0 = make_float2(acc[mt][nt][0], acc[mt][nt][1]);
            float2 v1 = make_float2(acc[mt][nt][2], acc[mt][nt][3]);
            *(float2*)&C[(size_t)row * N + col]       = v0;
            *(float2*)&C[(size_t)(row + 8) * N + col] = v1;
        }
    }
}

/* ---------------- prep: fp32 -> bf16 hi/lo split -------------------------- */
__global__ __launch_bounds__(256)
void split_kernel(const float* __restrict__ src, __nv_bfloat16* __restrict__ hi,
                  __nv_bfloat16* __restrict__ lo, int n)
{
    int i = blockIdx.x * blockDim.x + threadIdx.x;
    if (i < n) {
        __nv_bfloat16 h, l;
        split2(src[i], h, l);
        hi[i] = h; lo[i] = l;
    }
}

/* ---------------- prep: W[K,N] fp32 -> W^T[N,K] bf16 hi/lo ---------------- */
__global__ __launch_bounds__(256)
void transpose_split_kernel(const float* __restrict__ W,
                            __nv_bfloat16* __restrict__ Thi,
                            __nv_bfloat16* __restrict__ Tlo, int K, int N)
{
    __shared__ float t[32][33];
    const int n0 = blockIdx.x * 32, k0 = blockIdx.y * 32;
    const int tx = threadIdx.x, ty = threadIdx.y;   /* block (32,8) */
#pragma unroll
    for (int j = 0; j < 32; j += 8)
        t[ty + j][tx] = W[(size_t)(k0 + ty + j) * N + n0 + tx];
    __syncthreads();
#pragma unroll
    for (int j = 0; j < 32; j += 8) {
        const float v = t[tx][ty + j];
        const size_t o = (size_t)(n0 + ty + j) * K + k0 + tx;
        __nv_bfloat16 h, l;
        split2(v, h, l);
        Thi[o] = h; Tlo[o] = l;
    }
}

/* ---------------- packed f32x2 helpers (small fp32 GEMMs) ----------------- */
__device__ __forceinline__ unsigned long long ffma2(unsigned long long a,
                                                    unsigned long long b,
                                                    unsigned long long c)
{
    unsigned long long d;
    asm("fma.rn.f32x2 %0, %1, %2, %3;" : "=l"(d) : "l"(a), "l"(b), "l"(c));
    return d;
}
__device__ __forceinline__ unsigned long long pack2(float x)
{
    unsigned long long d;
    unsigned int b = __float_as_uint(x);
    asm("mov.b64 %0, {%1, %2};" : "=l"(d) : "r"(b), "r"(b));
    return d;
}
__device__ __forceinline__ void unpack2(unsigned long long v, float& lo, float& hi)
{
    unsigned int a, b;
    asm("mov.b64 {%0, %1}, %2;" : "=r"(a), "=r"(b) : "l"(v));
    lo = __uint_as_float(a);
    hi = __uint_as_float(b);
}

/* ---------------- tiled fp32x2 GEMM (small GEMMs) ------------------------- */
enum { EPI_STORE = 0, EPI_SOFTPLUS = 1 };

template <int BM, int BN, int BK, int TM, int TN, int EPI>
__global__ __launch_bounds__(256)
void sgemm_kernel(const float* __restrict__ A, const float* __restrict__ B,
                  float* __restrict__ C, const float* __restrict__ bias,
                  int M, int N, int K, int lda, int ldb, int ldc)
{
    static_assert((BM * BK) % 1024 == 0 && (BN * BK) % 1024 == 0, "tile loads");
    static_assert((BM / TM) * (BN / TN) == 256, "256 threads");
    static_assert(TN % 2 == 0 && TM % 4 == 0, "packing");

    __shared__ __align__(16) float As[BK][BM];
    __shared__ __align__(16) float Bs[BK][BN];

    const int tid = threadIdx.x;
    const int m0  = blockIdx.y * BM;
    const int n0  = blockIdx.x * BN;
    const int kchunk = K / gridDim.z;
    const int kbeg   = blockIdx.z * kchunk;
    C += (size_t)blockIdx.z * (size_t)M * (size_t)ldc;

    const int tx = tid & 15;
    const int ty = tid >> 4;

    const int APR = BK / 4;
    const int BPR = BN / 4;
    const int AIT = (BM * BK) / 1024;
    const int BIT = (BN * BK) / 1024;

    unsigned long long acc2[TM][TN / 2];
#pragma unroll
    for (int i = 0; i < TM; i++)
#pragma unroll
        for (int j = 0; j < TN / 2; j++) acc2[i][j] = 0ull;

    for (int kt = kbeg; kt < kbeg + kchunk; kt += BK) {
#pragma unroll
        for (int it = 0; it < AIT; it++) {
            const int u    = tid + it * 256;
            const int arow = u / APR;
            const int acol = (u % APR) * 4;
            float4 av = *reinterpret_cast<const float4*>(
                &A[(size_t)(m0 + arow) * lda + kt + acol]);
            As[acol + 0][arow] = av.x;
            As[acol + 1][arow] = av.y;
            As[acol + 2][arow] = av.z;
            As[acol + 3][arow] = av.w;
        }
#pragma unroll
        for (int it = 0; it < BIT; it++) {
            const int u    = tid + it * 256;
            const int brow = u / BPR;
            const int bcol = (u % BPR) * 4;
            float4 bv = make_float4(0.f, 0.f, 0.f, 0.f);
            if (n0 + bcol < N)
                bv = *reinterpret_cast<const float4*>(
                    &B[(size_t)(kt + brow) * ldb + n0 + bcol]);
            *reinterpret_cast<float4*>(&Bs[brow][bcol]) = bv;
        }
        __syncthreads();

#pragma unroll
        for (int k = 0; k < BK; k++) {
            unsigned long long ra2[TM];
#pragma unroll
            for (int i = 0; i < TM; i += 4) {
                float4 v = *reinterpret_cast<const float4*>(&As[k][ty * TM + i]);
                ra2[i + 0] = pack2(v.x);
                ra2[i + 1] = pack2(v.y);
                ra2[i + 2] = pack2(v.z);
                ra2[i + 3] = pack2(v.w);
            }
            unsigned long long rb2[TN / 2];
#pragma unroll
            for (int j = 0; j < TN / 2; j += 2) {
                ulonglong2 bv = *reinterpret_cast<const ulonglong2*>(
                    &Bs[k][tx * TN + j * 2]);
                rb2[j + 0] = bv.x;
                rb2[j + 1] = bv.y;
            }
#pragma unroll
            for (int i = 0; i < TM; i++)
#pragma unroll
                for (int j = 0; j < TN / 2; j++)
                    acc2[i][j] = ffma2(ra2[i], rb2[j], acc2[i][j]);
        }
        __syncthreads();
    }

#pragma unroll
    for (int i = 0; i < TM; i++) {
        const int gm = m0 + ty * TM + i;
#pragma unroll
        for (int j = 0; j < TN / 2; j++) {
            float v0, v1;
            unpack2(acc2[i][j], v0, v1);
            const int gn = n0 + tx * TN + 2 * j;
            if (gn < N) {
                if (EPI == EPI_SOFTPLUS) {
                    v0 += bias[gn];
                    v0 = (v0 > 20.f) ? v0 : log1pf(expf(v0));
                }
                C[(size_t)gm * ldc + gn] = v0;
            }
            if (gn + 1 < N) {
                if (EPI == EPI_SOFTPLUS) {
                    v1 += bias[gn + 1];
                    v1 = (v1 > 20.f) ? v1 : log1pf(expf(v1));
                }
                C[(size_t)gm * ldc + gn + 1] = v1;
            }
        }
    }
}

/* ---------------- reduce NSPLIT split-K partials ------------------------- */
__global__ __launch_bounds__(256)
void reduce_split_kernel(float* __restrict__ dst,
                         const float* __restrict__ src, int n)
{
    int i = blockIdx.x * blockDim.x + threadIdx.x;
    if (i < n) {
        float s = 0.f;
#pragma unroll
        for (int p = 0; p < NSPLIT; p++) s += src[(size_t)p * n + i];
        dst[i] = s;
    }
}

/* ---------------- causal depthwise conv (K=4) + bias + SiLU --------------- */
__global__ __launch_bounds__(256)
void conv_silu_kernel(const float* __restrict__ convw,
                      const float* __restrict__ convb)
{
    int idx = blockIdx.x * blockDim.x + threadIdx.x;
    if (idx >= NROWS * DINNER) return;
    const int d   = idx & (DINNER - 1);
    const int row = idx >> 11;
    const int l   = row & (L_SEQ - 1);
    const int b   = row >> 11;
    float acc = convb[d];
#pragma unroll
    for (int k = 0; k < 4; k++) {
        const int ls = l - 3 + k;
        if (ls >= 0)
            acc = fmaf(convw[d * 4 + k],
                       g_xz[(size_t)(b * L_SEQ + ls) * (2 * DINNER) + d], acc);
    }
    acc = acc / (1.f + __expf(-acc));
    g_xssm[idx] = acc;
}

/* ---------------- selective scan ------------------------------------------ */
#define SCAN_T 64
#define CPB    8
__global__ __launch_bounds__(256)
void scan_kernel(const float* __restrict__ A_log)
{
    __shared__ __align__(8) float sBC[SCAN_T][2 * DSTATE];
    __shared__ float sdt[SCAN_T][CPB];
    __shared__ float sx [SCAN_T][CPB];
    __shared__ float sy [SCAN_T][CPB];

    const int b    = blockIdx.y;
    const int d0   = blockIdx.x * CPB;
    const int tid  = threadIdx.x;
    const int w    = tid >> 5;
    const int lane = tid & 31;
    const int d    = d0 + w;

    const float a0 = -expf(A_log[(size_t)d * DSTATE + 2 * lane]);
    const float a1 = -expf(A_log[(size_t)d * DSTATE + 2 * lane + 1]);
    float h0 = 0.f, h1 = 0.f;
    const int rowbase = b * L_SEQ;

    for (int t0 = 0; t0 < L_SEQ; t0 += SCAN_T) {
        for (int i = tid; i < SCAN_T * 2 * DSTATE; i += 256) {
            const int t = i >> 7, j = i & 127;
            sBC[t][j] = g_xdbl[(size_t)(rowbase + t0 + t) * XDIM + DTRANK + j];
        }
        for (int i = tid; i < SCAN_T * CPB; i += 256) {
            const int t = i / CPB, c = i % CPB;
            const size_t r = (size_t)(rowbase + t0 + t) * DINNER + d0 + c;
            sdt[t][c] = g_dt[r];
            sx [t][c] = g_xssm[r];
        }
        __syncthreads();

        for (int t = 0; t < SCAN_T; t++) {
            const float dtv = sdt[t][w];
            const float xv  = sx [t][w];
            const float2 Bv = *reinterpret_cast<const float2*>(&sBC[t][2 * lane]);
            const float2 Cv = *reinterpret_cast<const float2*>(&sBC[t][DSTATE + 2 * lane]);
            const float dA0 = __expf(a0 * dtv);
            const float dA1 = __expf(a1 * dtv);
            const float dbx = dtv * xv;
            h0 = fmaf(dA0, h0, dbx * Bv.x);
            h1 = fmaf(dA1, h1, dbx * Bv.y);
            float s = fmaf(h1, Cv.y, h0 * Cv.x);
            s += __shfl_xor_sync(0xffffffffu, s, 16);
            s += __shfl_xor_sync(0xffffffffu, s, 8);
            s += __shfl_xor_sync(0xffffffffu, s, 4);
            s += __shfl_xor_sync(0xffffffffu, s, 2);
            s += __shfl_xor_sync(0xffffffffu, s, 1);
            if (lane == 0) sy[t][w] = s;
        }
        __syncthreads();

        for (int i = tid; i < SCAN_T * CPB; i += 256) {
            const int t = i / CPB, c = i % CPB;
            g_y[(size_t)(rowbase + t0 + t) * DINNER + d0 + c] = sy[t][c];
        }
        __syncthreads();
    }
}

/* -------- gating: y = (y + x_ssm*D) * silu(z), emitted as bf16 hi/lo ------ */
__global__ __launch_bounds__(256)
void gate_kernel(const float* __restrict__ Dvec)
{
    int idx = blockIdx.x * blockDim.x + threadIdx.x;
    if (idx >= NROWS * DINNER) return;
    const int d   = idx & (DINNER - 1);
    const int row = idx >> 11;
    const float z = g_xz[(size_t)row * (2 * DINNER) + DINNER + d];
    const float v = (g_y[idx] + g_xssm[idx] * Dvec[d]) * (z / (1.f + __expf(-z)));
    __nv_bfloat16 h, l;
    split2(v, h, l);
    g_yhi[idx] = h; g_ylo[idx] = l;
}

/* ---------------- host orchestration -------------------------------------- */
extern "C" void kernel_launch(void* const* d_in, const int* in_sizes, int n_in,
                              void* d_out, int out_size)
{
    const float* u     = (const float*)d_in[0];
    const float* W_in  = (const float*)d_in[1];
    const float* convw = (const float*)d_in[2];
    const float* convb = (const float*)d_in[3];
    const float* W_x   = (const float*)d_in[4];
    const float* W_dt  = (const float*)d_in[5];
    const float* b_dt  = (const float*)d_in[6];
    const float* A_log = (const float*)d_in[7];
    const float* Dvec  = (const float*)d_in[8];
    const float* W_out = (const float*)d_in[9];
    float* out = (float*)d_out;

    void* p;
    cudaGetSymbolAddress(&p, g_xz);    float* xz   = (float*)p;
    cudaGetSymbolAddress(&p, g_xssm);  float* xssm = (float*)p;
    cudaGetSymbolAddress(&p, g_xdbl);  float* xdbl = (float*)p;
    cudaGetSymbolAddress(&p, g_part);  float* part = (float*)p;
    cudaGetSymbolAddress(&p, g_dt);    float* dtb  = (float*)p;
    cudaGetSymbolAddress(&p, g_uhi);   __nv_bfloat16* uhi  = (__nv_bfloat16*)p;
    cudaGetSymbolAddress(&p, g_ulo);   __nv_bfloat16* ulo  = (__nv_bfloat16*)p;
    cudaGetSymbolAddress(&p, g_Wihi);  __nv_bfloat16* wihi = (__nv_bfloat16*)p;
    cudaGetSymbolAddress(&p, g_Wilo);  __nv_bfloat16* wilo = (__nv_bfloat16*)p;
    cudaGetSymbolAddress(&p, g_Wohi);  __nv_bfloat16* wohi = (__nv_bfloat16*)p;
    cudaGetSymbolAddress(&p, g_Wolo);  __nv_bfloat16* wolo = (__nv_bfloat16*)p;
    cudaGetSymbolAddress(&p, g_yhi);   __nv_bfloat16* yhi  = (__nv_bfloat16*)p;
    cudaGetSymbolAddress(&p, g_ylo);   __nv_bfloat16* ylo  = (__nv_bfloat16*)p;

    const int threads = 256;
    const int n_elem  = NROWS * DINNER;

    /* prep: split u; transpose+split W_in, W_out */
    split_kernel<<<(NROWS * DMODEL) / threads, threads>>>(u, uhi, ulo,
                                                          NROWS * DMODEL);
    transpose_split_kernel<<<dim3((2 * DINNER) / 32, DMODEL / 32), dim3(32, 8)>>>(
        W_in, wihi, wilo, DMODEL, 2 * DINNER);
    transpose_split_kernel<<<dim3(DMODEL / 32, DINNER / 32), dim3(32, 8)>>>(
        W_out, wohi, wolo, DINNER, DMODEL);

    /* 1. xz = u @ W_in   [4096,1024]x[1024,4096]  (HMMA bf16-split) */
    hmma_gemm_kernel<<<dim3((2 * DINNER) / HBN, NROWS / HBM), threads>>>(
        uhi, ulo, wihi, wilo, xz, NROWS, 2 * DINNER, DMODEL);

    /* 2. causal depthwise conv + SiLU -> x_ssm */
    conv_silu_kernel<<<n_elem / threads, threads>>>(convw, convb);

    /* 3. x_dbl = x_ssm @ W_x (split-K=8, deterministic partials)  N=192 */
    sgemm_kernel<64, 64, 16, 4, 4, EPI_STORE>
        <<<dim3(XDIM / 64, NROWS / 64, NSPLIT), threads>>>(
            xssm, W_x, part, nullptr, NROWS, XDIM, DINNER,
            DINNER, XDIM, XDIM);
    reduce_split_kernel<<<(NROWS * XDIM + threads - 1) / threads, threads>>>(
        xdbl, part, NROWS * XDIM);

    /* 4. dt = softplus(dt_r @ W_dt + b_dt)     K=64, A has lda=192 */
    sgemm_kernel<64, 64, 16, 4, 4, EPI_SOFTPLUS>
        <<<dim3(DINNER / 64, NROWS / 64, 1), threads>>>(
            xdbl, W_dt, dtb, b_dt, NROWS, DINNER, DTRANK,
            XDIM, DINNER, DINNER);

    /* 5. selective scan -> y */
    scan_kernel<<<dim3(DINNER / CPB, NBATCH), threads>>>(A_log);

    /* 6. gate -> y bf16 hi/lo */
    gate_kernel<<<n_elem / threads, threads>>>(Dvec);

    /* 7. out = y @ W_out  [4096,2048]x[2048,1024]  (HMMA bf16-split) */
    hmma_gemm_kernel<<<dim3(DMODEL / HBN, NROWS / HBM), threads>>>(
        yhi, ylo, wohi, wolo, out, NROWS, DMODEL, DINNER);
}